// round 16
// baseline (speedup 1.0000x reference)
#include <cuda_runtime.h>
#include <math.h>
#include <stdint.h>
#include <stddef.h>

#define BDIM 16384
#define CB   8
#define KK   256
#define DD   512
#define NCOL (CB*KK)              /* 2048 */
#define NIDX (BDIM*CB)            /* 131072 */
#define NXB  1024
#define XSTR 36                   /* smem row stride for mma tiles */
#define BCH  9216                 /* words per B chunk: Bh(4608)+Bl(4608) */

// fused-kernel bid map: 192-producer head, 116 groups of (16 prod + 128 frames), frame tail
#define HEADN   192               /* rowblocks 0..11 produced up front */
#define NGRP    116
#define GRPSZ   144
#define TAILB   (HEADN + NGRP*GRPSZ)
#define FUSE_GRID (TAILB + 12*128) /* 18432 = 2048 + 16384 */
#define FSM_BYTES 110592           /* x0mma smem: (2*4608 + 2*BCH)*4 */

// ---------------- static device scratch (no allocations allowed) ----------------
static __device__ float d_X0[(size_t)BDIM*NCOL];   // x @ centers^T       (134MB)
static __device__ float d_G2[(size_t)NCOL*NCOL];   // centers @ centers^T (16MB)
static __device__ float d_Pb[(size_t)BDIM*NCOL];   // per-frame probs, last iter (134MB)
static __device__ __align__(16) uint32_t d_Bp[16*16*BCH]; // prepacked TF32 B tiles (9.4MB)
static __device__ float d_censq[NCOL];
static __device__ int   d_idx[2][NIDX];
static __device__ float d_Hb[NIDX];
static __device__ float d_ESb[NIDX];
static __device__ float d_Pc[32][NCOL];
static __device__ float d_xsqp[NXB];
static __device__ unsigned d_flag[128];            // per-rowblock X0 completion (16 arrivals)

// ---------------- Threefry-2x32-20 (exact JAX semantics) ----------------
__host__ __device__ __forceinline__ unsigned rotl32(unsigned x, int r) {
    return (x << r) | (x >> (32 - r));
}
__host__ __device__ __forceinline__ void tf2x32(unsigned k0, unsigned k1,
                                                unsigned& x0, unsigned& x1) {
    unsigned k2 = k0 ^ k1 ^ 0x1BD11BDAu;
    x0 += k0; x1 += k1;
#define TFR(r) { x0 += x1; x1 = rotl32(x1, (r)); x1 ^= x0; }
    TFR(13) TFR(15) TFR(26) TFR(6)   x0 += k1; x1 += k2 + 1u;
    TFR(17) TFR(29) TFR(16) TFR(24)  x0 += k2; x1 += k0 + 2u;
    TFR(13) TFR(15) TFR(26) TFR(6)   x0 += k0; x1 += k1 + 3u;
    TFR(17) TFR(29) TFR(16) TFR(24)  x0 += k1; x1 += k2 + 4u;
    TFR(13) TFR(15) TFR(26) TFR(6)   x0 += k2; x1 += k0 + 5u;
#undef TFR
}

__device__ __forceinline__ float gumbel_from_bits(unsigned r) {
    float f = __uint_as_float((r >> 9) | 0x3f800000u) - 1.0f;
    float u = (f == 0.0f) ? 1.17549435e-38f : f;
    return -logf(-logf(u));
}

// jax_threefry_partitionable random_bits: elem e -> threefry(key,(0,e)), o0^o1
__device__ __forceinline__ float gumbel_elem(unsigned k0, unsigned k1, unsigned e) {
    unsigned x0 = 0u, x1 = e;
    tf2x32(k0, k1, x0, x1);
    return gumbel_from_bits(x0 ^ x1);
}

// ---------------- cp.async + mma helpers ----------------
__device__ __forceinline__ uint32_t smem_u32(const void* p) {
    uint32_t a;
    asm("{ .reg .u64 t; cvta.to.shared.u64 t, %1; cvt.u32.u64 %0, t; }" : "=r"(a) : "l"(p));
    return a;
}
#define CP_ASYNC16(d, s) asm volatile("cp.async.cg.shared.global [%0], [%1], 16;" :: "r"(d), "l"(s) : "memory")
#define CP_COMMIT()      asm volatile("cp.async.commit_group;" ::: "memory")
#define CP_WAIT0()       asm volatile("cp.async.wait_group 0;" ::: "memory")
#define CP_WAIT1()       asm volatile("cp.async.wait_group 1;" ::: "memory")

__device__ __forceinline__ uint32_t to_tf32(float v) {
    uint32_t r;
    asm("cvt.rna.tf32.f32 %0, %1;" : "=r"(r) : "f"(v));
    return r;
}
__device__ __forceinline__ void mma_tf32(float* c, const uint32_t* a,
                                         uint32_t b0, uint32_t b1) {
    asm volatile(
        "mma.sync.aligned.m16n8k8.row.col.f32.tf32.tf32.f32 "
        "{%0,%1,%2,%3}, {%4,%5,%6,%7}, {%8,%9}, {%0,%1,%2,%3};"
        : "+f"(c[0]), "+f"(c[1]), "+f"(c[2]), "+f"(c[3])
        : "r"(a[0]), "r"(a[1]), "r"(a[2]), "r"(a[3]), "r"(b0), "r"(b1));
}

// ---------------- small kernels ----------------
__global__ void censq_k(const float* __restrict__ centers) {
    int row = blockIdx.x;                  // 0..2047
    const float* cc = centers + (size_t)row * DD;
    float p = 0.0f;
    for (int d = threadIdx.x; d < DD; d += 128) p = fmaf(cc[d], cc[d], p);
    #pragma unroll
    for (int off = 16; off; off >>= 1) p += __shfl_xor_sync(0xffffffffu, p, off);
    __shared__ float red[4];
    if ((threadIdx.x & 31) == 0) red[threadIdx.x >> 5] = p;
    __syncthreads();
    if (threadIdx.x == 0) d_censq[row] = ((red[0] + red[1]) + (red[2] + red[3]));
}

__global__ void xsq_k(const float* __restrict__ x) {
    const size_t N = (size_t)BDIM * DD;
    float p = 0.0f;
    for (size_t i = (size_t)blockIdx.x * blockDim.x + threadIdx.x; i < N;
         i += (size_t)gridDim.x * blockDim.x)
        p = fmaf(x[i], x[i], p);
    #pragma unroll
    for (int off = 16; off; off >>= 1) p += __shfl_xor_sync(0xffffffffu, p, off);
    __shared__ float red[8];
    if ((threadIdx.x & 31) == 0) red[threadIdx.x >> 5] = p;
    __syncthreads();
    if (threadIdx.x == 0) {
        float s = 0.0f;
        #pragma unroll
        for (int w = 0; w < 8; w++) s += red[w];
        d_xsqp[blockIdx.x] = s;
    }
}

// ---------------- prepack centers into TF32 hi/lo tiles + zero flags ----------------
__global__ void bprep_k(const float* __restrict__ centers) {
    unsigned t = blockIdx.x * blockDim.x + threadIdx.x;   // < 2048*512
    if (t < 128) d_flag[t] = 0u;                          // re-zeroed every launch
    unsigned n = t >> 9, d = t & 511;
    float v = centers[(size_t)n * DD + d];
    uint32_t hi = to_tf32(v);
    uint32_t lo = to_tf32(v - __uint_as_float(hi));
    unsigned nblk = n >> 7, row = n & 127, kc = d >> 5, col = d & 31;
    unsigned base = (nblk * 16 + kc) * BCH;
    d_Bp[base + row * XSTR + col] = hi;
    d_Bp[base + 4608 + row * XSTR + col] = lo;
}

// ---------------- scalar SGEMM (round-7, proven; used for G2 only) ----------------
__global__ __launch_bounds__(256, 2)
void gemm_k(const float* __restrict__ A, const float* __restrict__ centers,
            float* __restrict__ out) {
    __shared__ float As[16][68];
    __shared__ float Bs[16][256];
    const int tid = threadIdx.x;
    const int w = tid >> 5, l = tid & 31;
    const int cy = blockIdx.y;
    const int r0 = blockIdx.x * 64;

    const int lr = tid >> 2, lq = tid & 3;
    const float* aP = A + (size_t)(r0 + lr) * DD + lq * 4;
    const int bk = tid >> 1, bd = (tid & 1) * 8;
    const float* b0P = centers + ((size_t)cy * KK + bk) * DD + bd;
    const float* b1P = centers + ((size_t)cy * KK + 128 + bk) * DD + bd;

    float acc[8][8];
    #pragma unroll
    for (int i = 0; i < 8; i++)
        #pragma unroll
        for (int j = 0; j < 8; j++) acc[i][j] = 0.0f;

    float4 a4 = *(const float4*)(aP);
    float4 q0 = *(const float4*)(b0P);
    float4 q1 = *(const float4*)(b0P + 4);
    float4 q2 = *(const float4*)(b1P);
    float4 q3 = *(const float4*)(b1P + 4);

    for (int kb = 0; kb < 32; kb++) {
        __syncthreads();
        As[lq*4+0][lr] = a4.x; As[lq*4+1][lr] = a4.y;
        As[lq*4+2][lr] = a4.z; As[lq*4+3][lr] = a4.w;
        Bs[bd+0][bk] = q0.x; Bs[bd+1][bk] = q0.y;
        Bs[bd+2][bk] = q0.z; Bs[bd+3][bk] = q0.w;
        Bs[bd+4][bk] = q1.x; Bs[bd+5][bk] = q1.y;
        Bs[bd+6][bk] = q1.z; Bs[bd+7][bk] = q1.w;
        Bs[bd+0][128+bk] = q2.x; Bs[bd+1][128+bk] = q2.y;
        Bs[bd+2][128+bk] = q2.z; Bs[bd+3][128+bk] = q2.w;
        Bs[bd+4][128+bk] = q3.x; Bs[bd+5][128+bk] = q3.y;
        Bs[bd+6][128+bk] = q3.z; Bs[bd+7][128+bk] = q3.w;
        __syncthreads();
        if (kb < 31) {
            const int d0 = (kb + 1) * 16;
            a4 = *(const float4*)(aP + d0);
            q0 = *(const float4*)(b0P + d0);
            q1 = *(const float4*)(b0P + d0 + 4);
            q2 = *(const float4*)(b1P + d0);
            q3 = *(const float4*)(b1P + d0 + 4);
        }
        #pragma unroll
        for (int d = 0; d < 16; d++) {
            float4 a0 = *(const float4*)&As[d][w*8];
            float4 a1 = *(const float4*)&As[d][w*8+4];
            float4 bb0 = *(const float4*)&Bs[d][l*8];
            float4 bb1 = *(const float4*)&Bs[d][l*8+4];
            float av[8] = {a0.x,a0.y,a0.z,a0.w,a1.x,a1.y,a1.z,a1.w};
            float bv[8] = {bb0.x,bb0.y,bb0.z,bb0.w,bb1.x,bb1.y,bb1.z,bb1.w};
            #pragma unroll
            for (int i = 0; i < 8; i++)
                #pragma unroll
                for (int j = 0; j < 8; j++)
                    acc[i][j] = fmaf(av[i], bv[j], acc[i][j]);
        }
    }

    #pragma unroll
    for (int i = 0; i < 8; i++) {
        float* o = out + (size_t)(r0 + w*8 + i) * NCOL + cy * KK + l * 8;
        float4 v0 = make_float4(acc[i][0], acc[i][1], acc[i][2], acc[i][3]);
        float4 v1 = make_float4(acc[i][4], acc[i][5], acc[i][6], acc[i][7]);
        *(float4*)o = v0;
        *(float4*)(o + 4) = v1;
    }
}

// ---------------- X0 GEMM body (round-12, bit-identical; bx/ny explicit) ----------------
__device__ void x0mma_body(const float* __restrict__ A, float* __restrict__ out,
                           int bx, int ny, char* smbase) {
    uint32_t* xsm = (uint32_t*)smbase;
    uint32_t* Ah  = xsm;                      // [128][XSTR]
    uint32_t* Al  = xsm + 4608;
    uint32_t* Bst = xsm + 2 * 4608;           // 2 stages x BCH (Bh | Bl)

    const int tid  = threadIdx.x;
    const int warp = tid >> 5, lane = tid & 31;
    const int g = lane >> 2, tg = lane & 3;
    const int mw = warp >> 2, nw = warp & 3;
    const int r0 = bx * 128;
    const uint32_t* gB = d_Bp + (size_t)ny * 16 * BCH;

    float acc[4][4][4];
    #pragma unroll
    for (int i = 0; i < 4; i++)
        #pragma unroll
        for (int j = 0; j < 4; j++)
            #pragma unroll
            for (int q = 0; q < 4; q++) acc[i][j][q] = 0.0f;

    const int lrow = tid >> 3;
    const int lkq  = (tid & 7) * 4;

    float4 av4[4];
    #pragma unroll
    for (int q = 0; q < 4; q++)
        av4[q] = *(const float4*)(A + (size_t)(r0 + q * 32 + lrow) * DD + lkq);
    {
        const float4* src = (const float4*)(gB);
        uint32_t dst = smem_u32(Bst);
        #pragma unroll
        for (int i = 0; i < 9; i++)
            CP_ASYNC16(dst + (uint32_t)(tid + i * 256) * 16, src + tid + i * 256);
        CP_COMMIT();
    }

    for (int kc = 0; kc < 16; kc++) {
        const int s = kc & 1;
        uint4 hv[4], lv[4];
        #pragma unroll
        for (int q = 0; q < 4; q++) {
            float4 v = av4[q];
            uint32_t h0 = to_tf32(v.x), h1 = to_tf32(v.y),
                     h2 = to_tf32(v.z), h3 = to_tf32(v.w);
            hv[q] = make_uint4(h0, h1, h2, h3);
            lv[q] = make_uint4(to_tf32(v.x - __uint_as_float(h0)),
                               to_tf32(v.y - __uint_as_float(h1)),
                               to_tf32(v.z - __uint_as_float(h2)),
                               to_tf32(v.w - __uint_as_float(h3)));
        }
        __syncthreads();
        #pragma unroll
        for (int q = 0; q < 4; q++) {
            int m = q * 32 + lrow;
            *(uint4*)&Ah[m * XSTR + lkq] = hv[q];
            *(uint4*)&Al[m * XSTR + lkq] = lv[q];
        }
        if (kc < 15) {
            const float4* src = (const float4*)(gB + (kc + 1) * BCH);
            uint32_t dst = smem_u32(Bst + (s ^ 1) * BCH);
            #pragma unroll
            for (int i = 0; i < 9; i++)
                CP_ASYNC16(dst + (uint32_t)(tid + i * 256) * 16, src + tid + i * 256);
            CP_COMMIT();
            #pragma unroll
            for (int q = 0; q < 4; q++)
                av4[q] = *(const float4*)(A + (size_t)(r0 + q * 32 + lrow) * DD
                                          + (kc + 1) * 32 + lkq);
            CP_WAIT1();
        } else {
            CP_WAIT0();
        }
        __syncthreads();

        const uint32_t* Bh = Bst + s * BCH;
        const uint32_t* Bl = Bh + 4608;
        #pragma unroll
        for (int ka = 0; ka < 4; ka++) {
            const int kb = ka * 8;
            uint32_t bh0[4], bh1[4], bl0[4], bl1[4];
            #pragma unroll
            for (int j = 0; j < 4; j++) {
                int nn = nw * 32 + j * 8 + g;
                bh0[j] = Bh[nn * XSTR + kb + tg];
                bh1[j] = Bh[nn * XSTR + kb + tg + 4];
                bl0[j] = Bl[nn * XSTR + kb + tg];
                bl1[j] = Bl[nn * XSTR + kb + tg + 4];
            }
            #pragma unroll
            for (int i = 0; i < 4; i++) {
                int mm = mw * 64 + i * 16;
                uint32_t ah[4], al[4];
                ah[0] = Ah[(mm + g) * XSTR + kb + tg];
                ah[1] = Ah[(mm + g + 8) * XSTR + kb + tg];
                ah[2] = Ah[(mm + g) * XSTR + kb + tg + 4];
                ah[3] = Ah[(mm + g + 8) * XSTR + kb + tg + 4];
                al[0] = Al[(mm + g) * XSTR + kb + tg];
                al[1] = Al[(mm + g + 8) * XSTR + kb + tg];
                al[2] = Al[(mm + g) * XSTR + kb + tg + 4];
                al[3] = Al[(mm + g + 8) * XSTR + kb + tg + 4];
                #pragma unroll
                for (int j = 0; j < 4; j++) {
                    mma_tf32(acc[i][j], ah, bl0[j], bl1[j]);
                    mma_tf32(acc[i][j], al, bh0[j], bh1[j]);
                    mma_tf32(acc[i][j], ah, bh0[j], bh1[j]);
                }
            }
        }
    }

    const int n0 = ny * 128;
    #pragma unroll
    for (int i = 0; i < 4; i++) {
        int m0 = r0 + mw * 64 + i * 16;
        #pragma unroll
        for (int j = 0; j < 4; j++) {
            int n = n0 + nw * 32 + j * 8 + tg * 2;
            *(float2*)(out + (size_t)(m0 + g) * NCOL + n) =
                make_float2(acc[i][j][0], acc[i][j][1]);
            *(float2*)(out + (size_t)(m0 + g + 8) * NCOL + n) =
                make_float2(acc[i][j][2], acc[i][j][3]);
        }
    }
}

// ---------------- fused 4-iteration refine body (round-14, bit-identical) ----------------
__device__ void iter4_body(const float* __restrict__ x, const float* __restrict__ centers,
                           const float* __restrict__ fes, const int* __restrict__ init_idx,
                           uint4 fk0s, uint4 fk1s, int b, char* smbase) {
    float* sm   = (float*)smbase;
    float* Ss   = sm;                         // 2048
    float* diag = sm + NCOL;                  // 2048
    float* X0s  = sm + 2 * NCOL;
    float* CSs  = sm + 3 * NCOL;
    float* cens = sm + 4 * NCOL;              // 8 x 512
    float* xe   = sm + 4 * NCOL + CB * DD;
    float* xs   = xe + DD;
    __shared__ int ids[CB];

    const int tid = threadIdx.x;
    const int w = tid >> 5, l = tid & 31;

    // wait for this frame's X0 rowblock (producers have strictly earlier bids)
    const int rb = b >> 7;
    if (tid == 0) {
        while (atomicAdd(&d_flag[rb], 0u) < 16u) __nanosleep(128);
    }
    __syncthreads();

    if (tid < CB) ids[tid] = init_idx[b * CB + tid];
    __syncthreads();

    const float scale = expf(fes[0]);

    for (int it = 0; it < 4; it++) {
        const unsigned fk0 = (it == 0) ? fk0s.x : (it == 1) ? fk0s.y
                           : (it == 2) ? fk0s.z : fk0s.w;
        const unsigned fk1 = (it == 0) ? fk1s.x : (it == 1) ? fk1s.y
                           : (it == 2) ? fk1s.z : fk1s.w;
        const int last = (it == 3);

        #pragma unroll
        for (int q = 0; q < 4; q++) {
            int t = tid + q * 256;            // 0..1023
            int c = t >> 7, f = t & 127;
            const float4* src = (const float4*)(centers + ((size_t)c * KK + ids[c]) * DD) + f;
            CP_ASYNC16(smem_u32(cens + c * DD + f * 4), src);
        }
        if (it == 0) {
            const float4* sx = (const float4*)(d_X0 + (size_t)b * NCOL);
            uint32_t dx = smem_u32(X0s);
            CP_ASYNC16(dx + tid * 16, sx + tid);
            CP_ASYNC16(dx + (tid + 256) * 16, sx + tid + 256);
            const float4* sc = (const float4*)(d_censq);
            uint32_t dc = smem_u32(CSs);
            CP_ASYNC16(dc + tid * 16, sc + tid);
            CP_ASYNC16(dc + (tid + 256) * 16, sc + tid + 256);
            if (tid < 128)
                CP_ASYNC16(smem_u32(xs + tid * 4),
                           (const float4*)(x + (size_t)b * DD) + tid);
        }
        CP_COMMIT();

        // S[col] = sum_c G2[row_c][col] in fixed c order; stash diagonal value
        int rowbase[CB];
        #pragma unroll
        for (int c = 0; c < CB; c++) rowbase[c] = c * KK + ids[c];
        #pragma unroll
        for (int q = 0; q < 8; q++) {
            int col = tid + q * 256;
            float s = 0.0f;
            float dg = 0.0f;
            #pragma unroll
            for (int c = 0; c < CB; c++) {
                float v = d_G2[(size_t)rowbase[c] * NCOL + col];
                if ((col >> 8) == c) dg = v;
                s += v;
            }
            Ss[col] = s;
            diag[col] = dg;
        }
        CP_WAIT0();
        __syncthreads();

        #pragma unroll
        for (int q = 0; q < 2; q++) {
            int d = tid + q * 256;
            float s = 0.0f;
            #pragma unroll
            for (int c = 0; c < CB; c++) s += cens[c * DD + d];
            xe[d] = s - xs[d];
        }
        __syncthreads();

        float asq = 0.0f;
        #pragma unroll
        for (int it2 = 0; it2 < 16; it2++) {
            int d = l + it2 * 32;
            float a = xe[d] - cens[w * DD + d];
            asq = fmaf(a, a, asq);
        }
        #pragma unroll
        for (int off = 16; off; off >>= 1)
            asq += __shfl_xor_sync(0xffffffffu, asq, off);

        const int c = w;
        const unsigned ebase = ((unsigned)(b * CB + c)) << 8;

        float vs[8];
        float bestS = -INFINITY; int bestK = 0;
        #pragma unroll
        for (int j = 0; j < 8; j++) {
            int k = l + 32 * j;
            int col = c * KK + k;
            float cross = (Ss[col] - X0s[col]) - diag[col];
            float v = -((asq + 2.0f * cross) + CSs[col]);   // reference grouping
            vs[j] = v;
            float g = gumbel_elem(fk0, fk1, ebase + (unsigned)k);
            float s = scale * v + g;
            if (s > bestS || (s == bestS && k < bestK)) { bestS = s; bestK = k; }
        }
        #pragma unroll
        for (int off = 16; off; off >>= 1) {
            float oS = __shfl_xor_sync(0xffffffffu, bestS, off);
            int   oK = __shfl_xor_sync(0xffffffffu, bestK, off);
            if (oS > bestS || (oS == bestS && oK < bestK)) { bestS = oS; bestK = oK; }
        }
        if (l == 0) {
            if (last) d_idx[0][b * CB + c] = bestK;
            else      ids[c] = bestK;
        }

        if (last) {
            float m = -INFINITY;
            #pragma unroll
            for (int j = 0; j < 8; j++) m = fmaxf(m, scale * vs[j]);
            #pragma unroll
            for (int off = 16; off; off >>= 1)
                m = fmaxf(m, __shfl_xor_sync(0xffffffffu, m, off));
            float se = 0.0f;
            #pragma unroll
            for (int j = 0; j < 8; j++) se += expf(scale * vs[j] - m);
            #pragma unroll
            for (int off = 16; off; off >>= 1)
                se += __shfl_xor_sync(0xffffffffu, se, off);
            float lse = m + logf(se);
            float H = 0.0f, ES = 0.0f;
            #pragma unroll
            for (int j = 0; j < 8; j++) {
                int k = l + 32 * j;
                float lp = scale * vs[j] - lse;
                float p = expf(lp);
                H  = fmaf(-p, lp, H);
                ES = fmaf(p, -vs[j], ES);
                d_Pb[(size_t)b * NCOL + c * KK + k] = p;
            }
            #pragma unroll
            for (int off = 16; off; off >>= 1) {
                H  += __shfl_xor_sync(0xffffffffu, H, off);
                ES += __shfl_xor_sync(0xffffffffu, ES, off);
            }
            if (l == 0) { d_Hb[b * CB + c] = H; d_ESb[b * CB + c] = ES; }
        }
        __syncthreads();
    }
}

// ---------------- fused kernel: x0mma producers + iter4 consumers, overlapped ----------------
__global__ void __launch_bounds__(256, 2)
fused_k(const float* __restrict__ x, const float* __restrict__ centers,
        const float* __restrict__ fes, const int* __restrict__ init_idx,
        float* __restrict__ X0out, uint4 fk0s, uint4 fk1s) {
    extern __shared__ char smbase[];
    const int bid = blockIdx.x;
    int m = -1, f = -1;
    if (bid < HEADN) {
        m = bid;                                    // rowblocks 0..11 up front
    } else if (bid < TAILB) {
        int g = (bid - HEADN) / GRPSZ, r = (bid - HEADN) % GRPSZ;
        if (r < 16) m = HEADN + g * 16 + r;         // rowblocks 12..127
        else        f = g * 128 + (r - 16);         // frames of rowblocks 0..115
    } else {
        f = NGRP * 128 + (bid - TAILB);             // frames of rowblocks 116..127
    }

    if (m >= 0) {
        x0mma_body(x, X0out, m >> 4, m & 15, smbase);
        __threadfence();
        __syncthreads();
        if (threadIdx.x == 0) atomicAdd(&d_flag[m >> 4], 1u);
    } else {
        iter4_body(x, centers, fes, init_idx, fk0s, fk1s, f, smbase);
    }
}

// ---------------- last-iter column sums of probs (deterministic) ----------------
__global__ void colsum_k() {
    const int col = blockIdx.y * 256 + threadIdx.x;
    const int bx = blockIdx.x;             // 32 b-chunks of 512
    float s = 0.0f;
    for (int b = bx * 512; b < (bx + 1) * 512; b++)
        s += d_Pb[(size_t)b * NCOL + col];
    d_Pc[bx][col] = s;
}

// ---------------- outputs ----------------
__global__ void outidx_k(float* out, int out_size) {
    int t = blockIdx.x * blockDim.x + threadIdx.x;
    if (t < NIDX && t < out_size) out[t] = (float)d_idx[0][t];
}

__global__ void scal_k(float* out, int out_size) {
    const int t = threadIdx.x;
    __shared__ float sh[256];

    float v = 0.0f;
    for (int i = t; i < NXB; i += 256) v += d_xsqp[i];
    sh[t] = v; __syncthreads();
    for (int s = 128; s; s >>= 1) { if (t < s) sh[t] += sh[t + s]; __syncthreads(); }
    float xsq = sh[0]; __syncthreads();

    v = 0.0f;
    for (int i = t; i < NIDX; i += 256) v += d_Hb[i];
    sh[t] = v; __syncthreads();
    for (int s = 128; s; s >>= 1) { if (t < s) sh[t] += sh[t + s]; __syncthreads(); }
    float Hs = sh[0]; __syncthreads();

    v = 0.0f;
    for (int i = t; i < NIDX; i += 256) v += d_ESb[i];
    sh[t] = v; __syncthreads();
    for (int s = 128; s; s >>= 1) { if (t < s) sh[t] += sh[t + s]; __syncthreads(); }
    float ESs = sh[0]; __syncthreads();

    v = 0.0f;
    for (int col = t; col < NCOL; col += 256) {
        float s = 0.0f;
        #pragma unroll
        for (int bx = 0; bx < 32; bx++) s += d_Pc[bx][col];
        float avg = s / (float)BDIM;
        v += -avg * logf(avg + 1e-20f);
    }
    sh[t] = v; __syncthreads();
    for (int s = 128; s; s >>= 1) { if (t < s) sh[t] += sh[t + s]; __syncthreads(); }
    float cent = sh[0];

    if (t == 0 && out_size >= NIDX + 3) {
        out[NIDX + 0] = logf((float)KK) - cent / (float)CB;  // entropy_loss
        out[NIDX + 1] = Hs / (float)NIDX;                    // frame_entropy
        out[NIDX + 2] = (ESs / (float)CB) / (xsq + 1e-20f);  // reconstruction_loss
    }
}

// ---------------- launch ----------------
extern "C" void kernel_launch(void* const* d_in, const int* in_sizes, int n_in,
                              void* d_out, int out_size) {
    const float* x       = (const float*)d_in[0];
    const float* centers = (const float*)d_in[1];
    const float* fes     = (const float*)d_in[2];
    const int*   init_i  = (const int*)d_in[3];
    float* out = (float*)d_out;
    (void)in_sizes; (void)n_in;

    static int smem_set = 0;
    if (!smem_set) {
        cudaFuncSetAttribute(fused_k, cudaFuncAttributeMaxDynamicSharedMemorySize,
                             FSM_BYTES);
        smem_set = 1;
    }

    censq_k<<<NCOL, 128>>>(centers);
    xsq_k<<<NXB, 256>>>(x);
    bprep_k<<<(NCOL * DD) / 256, 256>>>(centers);

    // G2 = CF @ CF^T (fp32 scalar, bit-stable)
    {
        float* G2p; cudaGetSymbolAddress((void**)&G2p, d_G2);
        dim3 gg(NCOL / 64, CB);
        gemm_k<<<gg, 256>>>(centers, centers, G2p);
    }

    // fused: X0 tensor GEMM (producers) overlapped with 4-iteration refinement
    {
        float* X0p; cudaGetSymbolAddress((void**)&X0p, d_X0);
        unsigned f0[4], f1[4];
        for (int i = 0; i < 4; i++) {
            unsigned a = 0u, b2 = (unsigned)i;
            tf2x32(0u, 1234u, a, b2);   // fold_in(key(1234), i)
            f0[i] = a; f1[i] = b2;
        }
        uint4 fk0s = make_uint4(f0[0], f0[1], f0[2], f0[3]);
        uint4 fk1s = make_uint4(f1[0], f1[1], f1[2], f1[3]);
        fused_k<<<FUSE_GRID, 256, FSM_BYTES>>>(x, centers, fes, init_i, X0p,
                                               fk0s, fk1s);
    }

    {
        dim3 gc(32, CB);
        colsum_k<<<gc, 256>>>();
    }
    outidx_k<<<(NIDX + 255) / 256, 256>>>(out, out_size);
    scal_k<<<1, 256>>>(out, out_size);
}

// round 17
// speedup vs baseline: 1.1460x; 1.1460x over previous
#include <cuda_runtime.h>
#include <math.h>
#include <stdint.h>
#include <stddef.h>

#define BDIM 16384
#define CB   8
#define KK   256
#define DD   512
#define NCOL (CB*KK)              /* 2048 */
#define NIDX (BDIM*CB)            /* 131072 */
#define NXB  1024
#define XSTR 36                   /* smem row stride for mma tiles */
#define BCH  9216                 /* words per B chunk: Bh(4608)+Bl(4608) */

// ---------------- static device scratch (no allocations allowed) ----------------
static __device__ float d_X0[(size_t)BDIM*NCOL];   // x @ centers^T       (134MB)
static __device__ float d_G2[(size_t)NCOL*NCOL];   // centers @ centers^T (16MB)
static __device__ float d_Pb[(size_t)BDIM*NCOL];   // per-frame probs, last iter (134MB)
static __device__ __align__(16) uint32_t d_Bp[16*16*BCH]; // prepacked TF32 B tiles (9.4MB)
static __device__ float d_censq[NCOL];
static __device__ int   d_idx[2][NIDX];
static __device__ float d_Hb[NIDX];
static __device__ float d_ESb[NIDX];
static __device__ float d_Pc[32][NCOL];
static __device__ float d_xsqp[NXB];

// ---------------- Threefry-2x32-20 (exact JAX semantics) ----------------
__host__ __device__ __forceinline__ unsigned rotl32(unsigned x, int r) {
    return (x << r) | (x >> (32 - r));
}
__host__ __device__ __forceinline__ void tf2x32(unsigned k0, unsigned k1,
                                                unsigned& x0, unsigned& x1) {
    unsigned k2 = k0 ^ k1 ^ 0x1BD11BDAu;
    x0 += k0; x1 += k1;
#define TFR(r) { x0 += x1; x1 = rotl32(x1, (r)); x1 ^= x0; }
    TFR(13) TFR(15) TFR(26) TFR(6)   x0 += k1; x1 += k2 + 1u;
    TFR(17) TFR(29) TFR(16) TFR(24)  x0 += k2; x1 += k0 + 2u;
    TFR(13) TFR(15) TFR(26) TFR(6)   x0 += k0; x1 += k1 + 3u;
    TFR(17) TFR(29) TFR(16) TFR(24)  x0 += k1; x1 += k2 + 4u;
    TFR(13) TFR(15) TFR(26) TFR(6)   x0 += k2; x1 += k0 + 5u;
#undef TFR
}

__device__ __forceinline__ float gumbel_from_bits(unsigned r) {
    float f = __uint_as_float((r >> 9) | 0x3f800000u) - 1.0f;
    float u = (f == 0.0f) ? 1.17549435e-38f : f;
    return -logf(-logf(u));
}

// jax_threefry_partitionable random_bits: elem e -> threefry(key,(0,e)), o0^o1
__device__ __forceinline__ float gumbel_elem(unsigned k0, unsigned k1, unsigned e) {
    unsigned x0 = 0u, x1 = e;
    tf2x32(k0, k1, x0, x1);
    return gumbel_from_bits(x0 ^ x1);
}

// ---------------- cp.async + mma helpers ----------------
__device__ __forceinline__ uint32_t smem_u32(const void* p) {
    uint32_t a;
    asm("{ .reg .u64 t; cvta.to.shared.u64 t, %1; cvt.u32.u64 %0, t; }" : "=r"(a) : "l"(p));
    return a;
}
#define CP_ASYNC16(d, s) asm volatile("cp.async.cg.shared.global [%0], [%1], 16;" :: "r"(d), "l"(s) : "memory")
#define CP_COMMIT()      asm volatile("cp.async.commit_group;" ::: "memory")
#define CP_WAIT0()       asm volatile("cp.async.wait_group 0;" ::: "memory")
#define CP_WAIT1()       asm volatile("cp.async.wait_group 1;" ::: "memory")

__device__ __forceinline__ uint32_t to_tf32(float v) {
    uint32_t r;
    asm("cvt.rna.tf32.f32 %0, %1;" : "=r"(r) : "f"(v));
    return r;
}
__device__ __forceinline__ void mma_tf32(float* c, const uint32_t* a,
                                         uint32_t b0, uint32_t b1) {
    asm volatile(
        "mma.sync.aligned.m16n8k8.row.col.f32.tf32.tf32.f32 "
        "{%0,%1,%2,%3}, {%4,%5,%6,%7}, {%8,%9}, {%0,%1,%2,%3};"
        : "+f"(c[0]), "+f"(c[1]), "+f"(c[2]), "+f"(c[3])
        : "r"(a[0]), "r"(a[1]), "r"(a[2]), "r"(a[3]), "r"(b0), "r"(b1));
}

// ---------------- small kernels ----------------
__global__ void censq_k(const float* __restrict__ centers) {
    int row = blockIdx.x;                  // 0..2047
    const float* cc = centers + (size_t)row * DD;
    float p = 0.0f;
    for (int d = threadIdx.x; d < DD; d += 128) p = fmaf(cc[d], cc[d], p);
    #pragma unroll
    for (int off = 16; off; off >>= 1) p += __shfl_xor_sync(0xffffffffu, p, off);
    __shared__ float red[4];
    if ((threadIdx.x & 31) == 0) red[threadIdx.x >> 5] = p;
    __syncthreads();
    if (threadIdx.x == 0) d_censq[row] = ((red[0] + red[1]) + (red[2] + red[3]));
}

__global__ void xsq_k(const float* __restrict__ x) {
    const size_t N = (size_t)BDIM * DD;
    float p = 0.0f;
    for (size_t i = (size_t)blockIdx.x * blockDim.x + threadIdx.x; i < N;
         i += (size_t)gridDim.x * blockDim.x)
        p = fmaf(x[i], x[i], p);
    #pragma unroll
    for (int off = 16; off; off >>= 1) p += __shfl_xor_sync(0xffffffffu, p, off);
    __shared__ float red[8];
    if ((threadIdx.x & 31) == 0) red[threadIdx.x >> 5] = p;
    __syncthreads();
    if (threadIdx.x == 0) {
        float s = 0.0f;
        #pragma unroll
        for (int w = 0; w < 8; w++) s += red[w];
        d_xsqp[blockIdx.x] = s;
    }
}

// ---------------- prepack centers into TF32 hi/lo tiles (smem-layout, padded) ----------------
__global__ void bprep_k(const float* __restrict__ centers) {
    unsigned t = blockIdx.x * blockDim.x + threadIdx.x;   // < 2048*512
    unsigned n = t >> 9, d = t & 511;
    float v = centers[(size_t)n * DD + d];
    uint32_t hi = to_tf32(v);
    uint32_t lo = to_tf32(v - __uint_as_float(hi));
    unsigned nblk = n >> 7, row = n & 127, kc = d >> 5, col = d & 31;
    unsigned base = (nblk * 16 + kc) * BCH;
    d_Bp[base + row * XSTR + col] = hi;
    d_Bp[base + 4608 + row * XSTR + col] = lo;
}

// ---------------- scalar SGEMM (round-7, proven; used for G2 only) ----------------
__global__ __launch_bounds__(256, 2)
void gemm_k(const float* __restrict__ A, const float* __restrict__ centers,
            float* __restrict__ out) {
    __shared__ float As[16][68];
    __shared__ float Bs[16][256];
    const int tid = threadIdx.x;
    const int w = tid >> 5, l = tid & 31;
    const int cy = blockIdx.y;
    const int r0 = blockIdx.x * 64;

    const int lr = tid >> 2, lq = tid & 3;
    const float* aP = A + (size_t)(r0 + lr) * DD + lq * 4;
    const int bk = tid >> 1, bd = (tid & 1) * 8;
    const float* b0P = centers + ((size_t)cy * KK + bk) * DD + bd;
    const float* b1P = centers + ((size_t)cy * KK + 128 + bk) * DD + bd;

    float acc[8][8];
    #pragma unroll
    for (int i = 0; i < 8; i++)
        #pragma unroll
        for (int j = 0; j < 8; j++) acc[i][j] = 0.0f;

    float4 a4 = *(const float4*)(aP);
    float4 q0 = *(const float4*)(b0P);
    float4 q1 = *(const float4*)(b0P + 4);
    float4 q2 = *(const float4*)(b1P);
    float4 q3 = *(const float4*)(b1P + 4);

    for (int kb = 0; kb < 32; kb++) {
        __syncthreads();
        As[lq*4+0][lr] = a4.x; As[lq*4+1][lr] = a4.y;
        As[lq*4+2][lr] = a4.z; As[lq*4+3][lr] = a4.w;
        Bs[bd+0][bk] = q0.x; Bs[bd+1][bk] = q0.y;
        Bs[bd+2][bk] = q0.z; Bs[bd+3][bk] = q0.w;
        Bs[bd+4][bk] = q1.x; Bs[bd+5][bk] = q1.y;
        Bs[bd+6][bk] = q1.z; Bs[bd+7][bk] = q1.w;
        Bs[bd+0][128+bk] = q2.x; Bs[bd+1][128+bk] = q2.y;
        Bs[bd+2][128+bk] = q2.z; Bs[bd+3][128+bk] = q2.w;
        Bs[bd+4][128+bk] = q3.x; Bs[bd+5][128+bk] = q3.y;
        Bs[bd+6][128+bk] = q3.z; Bs[bd+7][128+bk] = q3.w;
        __syncthreads();
        if (kb < 31) {
            const int d0 = (kb + 1) * 16;
            a4 = *(const float4*)(aP + d0);
            q0 = *(const float4*)(b0P + d0);
            q1 = *(const float4*)(b0P + d0 + 4);
            q2 = *(const float4*)(b1P + d0);
            q3 = *(const float4*)(b1P + d0 + 4);
        }
        #pragma unroll
        for (int d = 0; d < 16; d++) {
            float4 a0 = *(const float4*)&As[d][w*8];
            float4 a1 = *(const float4*)&As[d][w*8+4];
            float4 bb0 = *(const float4*)&Bs[d][l*8];
            float4 bb1 = *(const float4*)&Bs[d][l*8+4];
            float av[8] = {a0.x,a0.y,a0.z,a0.w,a1.x,a1.y,a1.z,a1.w};
            float bv[8] = {bb0.x,bb0.y,bb0.z,bb0.w,bb1.x,bb1.y,bb1.z,bb1.w};
            #pragma unroll
            for (int i = 0; i < 8; i++)
                #pragma unroll
                for (int j = 0; j < 8; j++)
                    acc[i][j] = fmaf(av[i], bv[j], acc[i][j]);
        }
    }

    #pragma unroll
    for (int i = 0; i < 8; i++) {
        float* o = out + (size_t)(r0 + w*8 + i) * NCOL + cy * KK + l * 8;
        float4 v0 = make_float4(acc[i][0], acc[i][1], acc[i][2], acc[i][3]);
        float4 v1 = make_float4(acc[i][4], acc[i][5], acc[i][6], acc[i][7]);
        *(float4*)o = v0;
        *(float4*)(o + 4) = v1;
    }
}

// ---------------- X0 GEMM on tensor cores: 3xTF32 mma.sync, pipelined (round-12) ----------------
__global__ __launch_bounds__(256, 2)
void x0mma_k(const float* __restrict__ A, float* __restrict__ out) {
    extern __shared__ uint32_t xsm[];
    uint32_t* Ah  = xsm;                      // [128][XSTR]
    uint32_t* Al  = xsm + 4608;
    uint32_t* Bst = xsm + 2 * 4608;           // 2 stages x BCH (Bh | Bl)

    const int tid  = threadIdx.x;
    const int warp = tid >> 5, lane = tid & 31;
    const int g = lane >> 2, tg = lane & 3;
    const int mw = warp >> 2, nw = warp & 3;
    const int r0 = blockIdx.x * 128;
    const uint32_t* gB = d_Bp + (size_t)blockIdx.y * 16 * BCH;

    float acc[4][4][4];
    #pragma unroll
    for (int i = 0; i < 4; i++)
        #pragma unroll
        for (int j = 0; j < 4; j++)
            #pragma unroll
            for (int q = 0; q < 4; q++) acc[i][j][q] = 0.0f;

    const int lrow = tid >> 3;
    const int lkq  = (tid & 7) * 4;

    float4 av4[4];
    #pragma unroll
    for (int q = 0; q < 4; q++)
        av4[q] = *(const float4*)(A + (size_t)(r0 + q * 32 + lrow) * DD + lkq);
    {
        const float4* src = (const float4*)(gB);
        uint32_t dst = smem_u32(Bst);
        #pragma unroll
        for (int i = 0; i < 9; i++)
            CP_ASYNC16(dst + (uint32_t)(tid + i * 256) * 16, src + tid + i * 256);
        CP_COMMIT();
    }

    for (int kc = 0; kc < 16; kc++) {
        const int s = kc & 1;
        uint4 hv[4], lv[4];
        #pragma unroll
        for (int q = 0; q < 4; q++) {
            float4 v = av4[q];
            uint32_t h0 = to_tf32(v.x), h1 = to_tf32(v.y),
                     h2 = to_tf32(v.z), h3 = to_tf32(v.w);
            hv[q] = make_uint4(h0, h1, h2, h3);
            lv[q] = make_uint4(to_tf32(v.x - __uint_as_float(h0)),
                               to_tf32(v.y - __uint_as_float(h1)),
                               to_tf32(v.z - __uint_as_float(h2)),
                               to_tf32(v.w - __uint_as_float(h3)));
        }
        __syncthreads();
        #pragma unroll
        for (int q = 0; q < 4; q++) {
            int m = q * 32 + lrow;
            *(uint4*)&Ah[m * XSTR + lkq] = hv[q];
            *(uint4*)&Al[m * XSTR + lkq] = lv[q];
        }
        if (kc < 15) {
            const float4* src = (const float4*)(gB + (kc + 1) * BCH);
            uint32_t dst = smem_u32(Bst + (s ^ 1) * BCH);
            #pragma unroll
            for (int i = 0; i < 9; i++)
                CP_ASYNC16(dst + (uint32_t)(tid + i * 256) * 16, src + tid + i * 256);
            CP_COMMIT();
            #pragma unroll
            for (int q = 0; q < 4; q++)
                av4[q] = *(const float4*)(A + (size_t)(r0 + q * 32 + lrow) * DD
                                          + (kc + 1) * 32 + lkq);
            CP_WAIT1();
        } else {
            CP_WAIT0();
        }
        __syncthreads();

        const uint32_t* Bh = Bst + s * BCH;
        const uint32_t* Bl = Bh + 4608;
        #pragma unroll
        for (int ka = 0; ka < 4; ka++) {
            const int kb = ka * 8;
            uint32_t bh0[4], bh1[4], bl0[4], bl1[4];
            #pragma unroll
            for (int j = 0; j < 4; j++) {
                int nn = nw * 32 + j * 8 + g;
                bh0[j] = Bh[nn * XSTR + kb + tg];
                bh1[j] = Bh[nn * XSTR + kb + tg + 4];
                bl0[j] = Bl[nn * XSTR + kb + tg];
                bl1[j] = Bl[nn * XSTR + kb + tg + 4];
            }
            #pragma unroll
            for (int i = 0; i < 4; i++) {
                int mm = mw * 64 + i * 16;
                uint32_t ah[4], al[4];
                ah[0] = Ah[(mm + g) * XSTR + kb + tg];
                ah[1] = Ah[(mm + g + 8) * XSTR + kb + tg];
                ah[2] = Ah[(mm + g) * XSTR + kb + tg + 4];
                ah[3] = Ah[(mm + g + 8) * XSTR + kb + tg + 4];
                al[0] = Al[(mm + g) * XSTR + kb + tg];
                al[1] = Al[(mm + g + 8) * XSTR + kb + tg];
                al[2] = Al[(mm + g) * XSTR + kb + tg + 4];
                al[3] = Al[(mm + g + 8) * XSTR + kb + tg + 4];
                #pragma unroll
                for (int j = 0; j < 4; j++) {
                    mma_tf32(acc[i][j], ah, bl0[j], bl1[j]);
                    mma_tf32(acc[i][j], al, bh0[j], bh1[j]);
                    mma_tf32(acc[i][j], ah, bh0[j], bh1[j]);
                }
            }
        }
    }

    const int n0 = blockIdx.y * 128;
    #pragma unroll
    for (int i = 0; i < 4; i++) {
        int m0 = r0 + mw * 64 + i * 16;
        #pragma unroll
        for (int j = 0; j < 4; j++) {
            int n = n0 + nw * 32 + j * 8 + tg * 2;
            *(float2*)(out + (size_t)(m0 + g) * NCOL + n) =
                make_float2(acc[i][j][0], acc[i][j][1]);
            *(float2*)(out + (size_t)(m0 + g + 8) * NCOL + n) =
                make_float2(acc[i][j][2], acc[i][j][3]);
        }
    }
}

// ---------------- fused 4-iteration refine: one block owns one frame (round-14) ----------------
// smem floats: Ss 2048 | diag 2048 | X0s 2048 | CSs 2048 | cens 8*512 | xe 512 | xs 512
#define ISM_FLOATS (4*NCOL + CB*DD + DD + DD)
__global__ void __launch_bounds__(256)
iter4_k(const float* __restrict__ x, const float* __restrict__ centers,
        const float* __restrict__ fes, const int* __restrict__ init_idx,
        uint4 fk0s, uint4 fk1s) {
    extern __shared__ float sm[];
    float* Ss   = sm;                         // 2048
    float* diag = sm + NCOL;                  // 2048
    float* X0s  = sm + 2 * NCOL;
    float* CSs  = sm + 3 * NCOL;
    float* cens = sm + 4 * NCOL;              // 8 x 512
    float* xe   = sm + 4 * NCOL + CB * DD;
    float* xs   = xe + DD;
    __shared__ int ids[CB];

    const int tid = threadIdx.x;
    const int w = tid >> 5, l = tid & 31;
    const int b = blockIdx.x;

    if (tid < CB) ids[tid] = init_idx[b * CB + tid];
    __syncthreads();

    const float scale = expf(fes[0]);

    for (int it = 0; it < 4; it++) {
        const unsigned fk0 = (it == 0) ? fk0s.x : (it == 1) ? fk0s.y
                           : (it == 2) ? fk0s.z : fk0s.w;
        const unsigned fk1 = (it == 0) ? fk1s.x : (it == 1) ? fk1s.y
                           : (it == 2) ? fk1s.z : fk1s.w;
        const int last = (it == 3);

        // gather (ids-dependent): 8 center rows; iter 0 also X0/censq/x
        #pragma unroll
        for (int q = 0; q < 4; q++) {
            int t = tid + q * 256;            // 0..1023
            int c = t >> 7, f = t & 127;
            const float4* src = (const float4*)(centers + ((size_t)c * KK + ids[c]) * DD) + f;
            CP_ASYNC16(smem_u32(cens + c * DD + f * 4), src);
        }
        if (it == 0) {
            const float4* sx = (const float4*)(d_X0 + (size_t)b * NCOL);
            uint32_t dx = smem_u32(X0s);
            CP_ASYNC16(dx + tid * 16, sx + tid);
            CP_ASYNC16(dx + (tid + 256) * 16, sx + tid + 256);
            const float4* sc = (const float4*)(d_censq);
            uint32_t dc = smem_u32(CSs);
            CP_ASYNC16(dc + tid * 16, sc + tid);
            CP_ASYNC16(dc + (tid + 256) * 16, sc + tid + 256);
            if (tid < 128)
                CP_ASYNC16(smem_u32(xs + tid * 4),
                           (const float4*)(x + (size_t)b * DD) + tid);
        }
        CP_COMMIT();

        // S[col] = sum_c G2[row_c][col] in fixed c order (direct LDG, coalesced);
        // stash the diagonal-block value (c == col>>8) -> bit-identical to staged version.
        int rowbase[CB];
        #pragma unroll
        for (int c = 0; c < CB; c++) rowbase[c] = c * KK + ids[c];
        #pragma unroll
        for (int q = 0; q < 8; q++) {
            int col = tid + q * 256;
            float s = 0.0f;
            float dg = 0.0f;
            #pragma unroll
            for (int c = 0; c < CB; c++) {
                float v = d_G2[(size_t)rowbase[c] * NCOL + col];
                if ((col >> 8) == c) dg = v;
                s += v;
            }
            Ss[col] = s;
            diag[col] = dg;
        }
        CP_WAIT0();
        __syncthreads();

        // xe[d] = (sum_c cens) - x[d]   (same arithmetic/order as before)
        #pragma unroll
        for (int q = 0; q < 2; q++) {
            int d = tid + q * 256;
            float s = 0.0f;
            #pragma unroll
            for (int c = 0; c < CB; c++) s += cens[c * DD + d];
            xe[d] = s - xs[d];
        }
        __syncthreads();

        // a_sq: warp-per-codebook (full-warp value after shuffle)
        float asq = 0.0f;
        #pragma unroll
        for (int it2 = 0; it2 < 16; it2++) {
            int d = l + it2 * 32;
            float a = xe[d] - cens[w * DD + d];
            asq = fmaf(a, a, asq);
        }
        #pragma unroll
        for (int off = 16; off; off >>= 1)
            asq += __shfl_xor_sync(0xffffffffu, asq, off);

        // logits + gumbel + argmax (+stats on last iter) — verbatim math
        const int c = w;
        const unsigned ebase = ((unsigned)(b * CB + c)) << 8;

        float vs[8];
        float bestS = -INFINITY; int bestK = 0;
        #pragma unroll
        for (int j = 0; j < 8; j++) {
            int k = l + 32 * j;
            int col = c * KK + k;
            float cross = (Ss[col] - X0s[col]) - diag[col];
            float v = -((asq + 2.0f * cross) + CSs[col]);   // reference grouping
            vs[j] = v;
            float g = gumbel_elem(fk0, fk1, ebase + (unsigned)k);
            float s = scale * v + g;
            if (s > bestS || (s == bestS && k < bestK)) { bestS = s; bestK = k; }
        }
        #pragma unroll
        for (int off = 16; off; off >>= 1) {
            float oS = __shfl_xor_sync(0xffffffffu, bestS, off);
            int   oK = __shfl_xor_sync(0xffffffffu, bestK, off);
            if (oS > bestS || (oS == bestS && oK < bestK)) { bestS = oS; bestK = oK; }
        }
        if (l == 0) {
            if (last) d_idx[0][b * CB + c] = bestK;
            else      ids[c] = bestK;
        }

        if (last) {
            float m = -INFINITY;
            #pragma unroll
            for (int j = 0; j < 8; j++) m = fmaxf(m, scale * vs[j]);
            #pragma unroll
            for (int off = 16; off; off >>= 1)
                m = fmaxf(m, __shfl_xor_sync(0xffffffffu, m, off));
            float se = 0.0f;
            #pragma unroll
            for (int j = 0; j < 8; j++) se += expf(scale * vs[j] - m);
            #pragma unroll
            for (int off = 16; off; off >>= 1)
                se += __shfl_xor_sync(0xffffffffu, se, off);
            float lse = m + logf(se);
            float H = 0.0f, ES = 0.0f;
            #pragma unroll
            for (int j = 0; j < 8; j++) {
                int k = l + 32 * j;
                float lp = scale * vs[j] - lse;
                float p = expf(lp);
                H  = fmaf(-p, lp, H);
                ES = fmaf(p, -vs[j], ES);
                d_Pb[(size_t)b * NCOL + c * KK + k] = p;
            }
            #pragma unroll
            for (int off = 16; off; off >>= 1) {
                H  += __shfl_xor_sync(0xffffffffu, H, off);
                ES += __shfl_xor_sync(0xffffffffu, ES, off);
            }
            if (l == 0) { d_Hb[b * CB + c] = H; d_ESb[b * CB + c] = ES; }
        }
        __syncthreads();   // ids visible; all smem reads done before next gather
    }
}

// ---------------- last-iter column sums of probs (deterministic) ----------------
__global__ void colsum_k() {
    const int col = blockIdx.y * 256 + threadIdx.x;
    const int bx = blockIdx.x;             // 32 b-chunks of 512
    float s = 0.0f;
    for (int b = bx * 512; b < (bx + 1) * 512; b++)
        s += d_Pb[(size_t)b * NCOL + col];
    d_Pc[bx][col] = s;
}

// ---------------- outputs ----------------
__global__ void outidx_k(float* out, int out_size) {
    int t = blockIdx.x * blockDim.x + threadIdx.x;
    if (t < NIDX && t < out_size) out[t] = (float)d_idx[0][t];
}

__global__ void scal_k(float* out, int out_size) {
    const int t = threadIdx.x;
    __shared__ float sh[256];

    float v = 0.0f;
    for (int i = t; i < NXB; i += 256) v += d_xsqp[i];
    sh[t] = v; __syncthreads();
    for (int s = 128; s; s >>= 1) { if (t < s) sh[t] += sh[t + s]; __syncthreads(); }
    float xsq = sh[0]; __syncthreads();

    v = 0.0f;
    for (int i = t; i < NIDX; i += 256) v += d_Hb[i];
    sh[t] = v; __syncthreads();
    for (int s = 128; s; s >>= 1) { if (t < s) sh[t] += sh[t + s]; __syncthreads(); }
    float Hs = sh[0]; __syncthreads();

    v = 0.0f;
    for (int i = t; i < NIDX; i += 256) v += d_ESb[i];
    sh[t] = v; __syncthreads();
    for (int s = 128; s; s >>= 1) { if (t < s) sh[t] += sh[t + s]; __syncthreads(); }
    float ESs = sh[0]; __syncthreads();

    v = 0.0f;
    for (int col = t; col < NCOL; col += 256) {
        float s = 0.0f;
        #pragma unroll
        for (int bx = 0; bx < 32; bx++) s += d_Pc[bx][col];
        float avg = s / (float)BDIM;
        v += -avg * logf(avg + 1e-20f);
    }
    sh[t] = v; __syncthreads();
    for (int s = 128; s; s >>= 1) { if (t < s) sh[t] += sh[t + s]; __syncthreads(); }
    float cent = sh[0];

    if (t == 0 && out_size >= NIDX + 3) {
        out[NIDX + 0] = logf((float)KK) - cent / (float)CB;  // entropy_loss
        out[NIDX + 1] = Hs / (float)NIDX;                    // frame_entropy
        out[NIDX + 2] = (ESs / (float)CB) / (xsq + 1e-20f);  // reconstruction_loss
    }
}

// ---------------- launch ----------------
extern "C" void kernel_launch(void* const* d_in, const int* in_sizes, int n_in,
                              void* d_out, int out_size) {
    const float* x       = (const float*)d_in[0];
    const float* centers = (const float*)d_in[1];
    const float* fes     = (const float*)d_in[2];
    const int*   init_i  = (const int*)d_in[3];
    float* out = (float*)d_out;
    (void)in_sizes; (void)n_in;

    static cudaStream_t s2 = 0;
    static cudaEvent_t evF = 0, evJ = 0;
    static int once = 0;
    if (!once) {
        cudaFuncSetAttribute(iter4_k, cudaFuncAttributeMaxDynamicSharedMemorySize,
                             ISM_FLOATS * 4);
        cudaFuncSetAttribute(x0mma_k, cudaFuncAttributeMaxDynamicSharedMemorySize,
                             (2 * 4608 + 2 * BCH) * 4);
        cudaStreamCreateWithFlags(&s2, cudaStreamNonBlocking);
        cudaEventCreateWithFlags(&evF, cudaEventDisableTiming);
        cudaEventCreateWithFlags(&evJ, cudaEventDisableTiming);
        once = 1;
    }

    // fork: G2 = CF @ CF^T (fp32 scalar, fma-bound) on s2 — independent of the
    // bprep/x0mma chain; overlaps x0mma's tensor-bound waves / tail gaps.
    cudaEventRecord(evF, 0);
    cudaStreamWaitEvent(s2, evF, 0);
    {
        float* G2p; cudaGetSymbolAddress((void**)&G2p, d_G2);
        dim3 gg(NCOL / 64, CB);
        gemm_k<<<gg, 256, 0, s2>>>(centers, centers, G2p);
    }
    cudaEventRecord(evJ, s2);

    censq_k<<<NCOL, 128>>>(centers);
    xsq_k<<<NXB, 256>>>(x);
    bprep_k<<<(NCOL * DD) / 256, 256>>>(centers);

    // X0 = x @ CF^T (3xTF32 mma, tensor-bound)
    {
        float* X0p; cudaGetSymbolAddress((void**)&X0p, d_X0);
        dim3 gx(BDIM / 128, NCOL / 128);
        x0mma_k<<<gx, 256, (2 * 4608 + 2 * BCH) * 4>>>(x, X0p);
    }

    // join: iter4 needs G2
    cudaStreamWaitEvent(0, evJ, 0);

    // fused 4-iteration refinement (one block per frame)
    {
        unsigned f0[4], f1[4];
        for (int i = 0; i < 4; i++) {
            unsigned a = 0u, b2 = (unsigned)i;
            tf2x32(0u, 1234u, a, b2);   // fold_in(key(1234), i)
            f0[i] = a; f1[i] = b2;
        }
        uint4 fk0s = make_uint4(f0[0], f0[1], f0[2], f0[3]);
        uint4 fk1s = make_uint4(f1[0], f1[1], f1[2], f1[3]);
        iter4_k<<<BDIM, 256, ISM_FLOATS * 4>>>(x, centers, fes, init_i, fk0s, fk1s);
    }

    {
        dim3 gc(32, CB);
        colsum_k<<<gc, 256>>>();
    }
    outidx_k<<<(NIDX + 255) / 256, 256>>>(out, out_size);
    scal_k<<<1, 256>>>(out, out_size);
}